// round 16
// baseline (speedup 1.0000x reference)
#include <cuda_runtime.h>
#include <math_constants.h>

// StratifiedMaxPooling: out[b,c] = max_{j: labels[j]==c} values[b,j]
// values: [B=128, N=200000] f32, labels: [N] int32, C=100.
//
// R16: static-schedule scatter (no ballot/ffs/dynamic loops at all).
//  - 148 blocks (1/SM) x 512 thr = 16 warps = 4 rowgroups x 4 streams.
//    Block covers ALL 128 rows; tiles of 32 columns, ~42 tiles/block.
//  - Stream s owns FIXED cols 8s..8s+7 of each tile (unrolled x8, branch-
//    free). Cross-stream same-class races eliminated by 4 acc copies
//    (one per stream): acc[s][row][class], merged at flush.
//  - Within a stream: rowgroups own disjoint rows; same warp+lane updates
//    its classes in program order => race-free, no conflict machinery.
//  - Bank-conflict-free: stage [col][row] pitch 129 ((c+lane)%32 distinct),
//    acc pitch 101 ((5*lane+k)%32 distinct), fill STS (4q+i+row)%32 distinct.
//  - Flush: merge 4 copies in smem -> coalesced STG to per-block scratch;
//    tiny reduce kernel maxes 148 L2-resident partials. NO global atomics,
//    no device-global state carried across replays.

#define FULL 0xFFFFFFFFu

static const int NBLK   = 148;
static const int NTHR   = 512;          // 16 warps
static const int C_NUM  = 100;
static const int C_PAD  = 101;
static const int B_NUM  = 128;
static const int NOUT   = B_NUM * C_NUM;      // 12800
static const int TILE   = 32;                 // columns per tile
static const int RPITCH = 129;                // stage row pitch (cols stride)
static const int ACC_STRIDE = B_NUM * C_PAD;  // 12928 floats per copy
static const int STG_F  = TILE * RPITCH;      // 4128 floats

__device__ float g_part[NBLK * NOUT];   // 7.6 MB per-block partials

__global__ __launch_bounds__(NTHR, 1)
void pool_kernel(const float* __restrict__ values,
                 const int*   __restrict__ labels,
                 int N, int ntiles)
{
    extern __shared__ __align__(16) float sdyn[];
    float* const acc   = sdyn;                       // [4][ACC_STRIDE]
    float* const stage = sdyn + 4 * ACC_STRIDE;      // [TILE][RPITCH]
    int*   const scl   = (int*)(stage + STG_F);      // [TILE]

    const int tid  = threadIdx.x;
    const int lane = tid & 31;
    const int warp = tid >> 5;
    const int rg   = warp & 3;          // rowgroup 0..3 (32 rows each)
    const int s    = warp >> 2;         // stream 0..3 (8 cols each)
    const int row  = rg * 32 + lane;

    for (int i = tid; i < 4 * ACC_STRIDE; i += NTHR) acc[i] = -CUDART_INF_F;

    // ---- fill mapping: thread -> rows {frow, frow+64}, col-quad q
    const int frow = tid >> 3;          // 0..63
    const int q    = tid & 7;           // quad: cols 4q..4q+3
    const float* const v0p = values + (size_t)frow * N + 4 * q;
    const float* const v1p = values + (size_t)(frow + 64) * N + 4 * q;
    float* const sfill = stage + (4 * q) * RPITCH + frow;  // +64 for v1 rows

    // ---- process mapping
    float* const accrow = acc + s * ACC_STRIDE + row * C_PAD;
    const float* const strow = stage + row;
    const int cbase = 8 * s;            // my 8 fixed columns

    // ---- prefetch tile t0 into registers
    int t = blockIdx.x;
    float4 a0, a1;
    int lb = 0;
    {
        a0 = __ldcs(reinterpret_cast<const float4*>(v0p + (size_t)t * TILE));
        a1 = __ldcs(reinterpret_cast<const float4*>(v1p + (size_t)t * TILE));
        if (tid < TILE) lb = labels[t * TILE + tid];
    }

    while (true) {
        __syncthreads();   // previous tile processed (and acc init done)

        // fill stage from prefetched registers
        sfill[0]          = a0.x;
        sfill[RPITCH]     = a0.y;
        sfill[2 * RPITCH] = a0.z;
        sfill[3 * RPITCH] = a0.w;
        float* sf1 = sfill + 64;
        sf1[0]          = a1.x;
        sf1[RPITCH]     = a1.y;
        sf1[2 * RPITCH] = a1.z;
        sf1[3 * RPITCH] = a1.w;
        if (tid < TILE) scl[tid] = lb;

        // prefetch next tile (overlaps the process phase below)
        const int tn = t + NBLK;
        const bool hn = tn < ntiles;
        if (hn) {
            a0 = __ldcs(reinterpret_cast<const float4*>(v0p + (size_t)tn * TILE));
            a1 = __ldcs(reinterpret_cast<const float4*>(v1p + (size_t)tn * TILE));
            if (tid < TILE) lb = labels[tn * TILE + tid];
        }

        __syncthreads();   // stage + scl ready

        // process my 8 fixed columns, fully unrolled, branch-free
#pragma unroll
        for (int j = 0; j < 8; j++) {
            const int c = cbase + j;
            const int k = scl[c];                  // broadcast LDS
            const float x = strow[c * RPITCH];     // conflict-free LDS
            float* const a = accrow + k;
            *a = fmaxf(*a, x);                     // same-lane ordered RMW
        }

        if (!hn) break;
        t = tn;
    }

    __syncthreads();   // all streams/rowgroups done

    // ---- merge 4 copies, write coalesced per-block partial
    float* const gp = g_part + (size_t)blockIdx.x * NOUT;
    for (int i = tid; i < NOUT; i += NTHR) {
        const int r = i / C_NUM;
        const int c = i - r * C_NUM;
        const int o = r * C_PAD + c;
        float m = fmaxf(fmaxf(acc[o], acc[ACC_STRIDE + o]),
                        fmaxf(acc[2 * ACC_STRIDE + o], acc[3 * ACC_STRIDE + o]));
        gp[i] = m;
    }
}

__global__ void reduce_kernel(float* __restrict__ out)
{
    const int i = blockIdx.x * blockDim.x + threadIdx.x;
    if (i >= NOUT) return;
    const float* p = g_part + i;
    float m = -CUDART_INF_F;
#pragma unroll 8
    for (int b = 0; b < NBLK; b++)
        m = fmaxf(m, p[(size_t)b * NOUT]);   // coalesced, L2-resident
    out[i] = m;
}

extern "C" void kernel_launch(void* const* d_in, const int* in_sizes, int n_in,
                              void* d_out, int out_size)
{
    const float* values = (const float*)d_in[0];
    const int*   labels = (const int*)d_in[1];
    const int N = in_sizes[1];          // 200000
    const int ntiles = N / TILE;        // 6250 exact

    const int dyn_bytes = (4 * ACC_STRIDE + STG_F) * (int)sizeof(float)
                        + TILE * (int)sizeof(int);   // 223,488 B
    cudaFuncSetAttribute(pool_kernel,
                         cudaFuncAttributeMaxDynamicSharedMemorySize,
                         dyn_bytes);

    pool_kernel<<<NBLK, NTHR, dyn_bytes>>>(values, labels, N, ntiles);
    reduce_kernel<<<(NOUT + 255) / 256, 256>>>((float*)d_out);
}